// round 17
// baseline (speedup 1.0000x reference)
#include <cuda_runtime.h>
#include <cstdint>

#define B_  2
#define N_  1024
#define M_  1024
#define H_  128
#define SCALE_ (1.0f / 6.964404506368992f)  // 1 / 128^0.4

__device__ float g_wpart[8 * H_];     // partial column sums of W (8 blocks)
__device__ float g_es[B_ * M_];       // exp(scaled logits)
__device__ float g_psum[64];          // per-K1-block partial exp sums (32/batch)

// ---------------------------------------------------------------------------
// K0: partial colsums of W. grid 8 x 512; block b handles rows [b*16, b*16+16).
// ---------------------------------------------------------------------------
__global__ __launch_bounds__(512) void k_wpart(const float* __restrict__ W) {
    __shared__ float4 sh[512];
    const int tid = threadIdx.x;
    const int blk = blockIdx.x;

    cudaTriggerProgrammaticLaunchCompletion();   // let K1 launch immediately

    sh[tid] = reinterpret_cast<const float4*>(W)[(blk * 16 + (tid >> 5)) * 32 + (tid & 31)];
    __syncthreads();
    if (tid < 32) {
        float4 s = make_float4(0.f, 0.f, 0.f, 0.f);
        #pragma unroll
        for (int r = 0; r < 16; ++r) {
            float4 p = sh[r * 32 + tid];
            s.x += p.x; s.y += p.y; s.z += p.z; s.w += p.w;
        }
        __stcg(reinterpret_cast<float4*>(g_wpart) + blk * 32 + tid, s);
    }
}

// ---------------------------------------------------------------------------
// K1: prologue loads keys rows (overlaps K0), then wcol reduce + dot + exp.
// grid 64 x 1024; one warp per key row (32 rows per block).
// ---------------------------------------------------------------------------
__global__ __launch_bounds__(1024) void k_exps(const float* __restrict__ keys) {
    __shared__ float sh_wcol[H_];
    __shared__ float sh_e[32];

    const int tid  = threadIdx.x;
    const int lane = tid & 31;
    const int warp = tid >> 5;
    const int blk  = blockIdx.x;

    cudaTriggerProgrammaticLaunchCompletion();   // let K2 launch immediately

    // prologue: cold keys read, overlapped with K0 execution
    const int row = blk * 32 + warp;             // [0, 2048)
    const float4 k4 = reinterpret_cast<const float4*>(keys)[row * 32 + lane];

    // wait for K0 grid completion
    cudaGridDependencySynchronize();

    // wcol[c] = sum of 8 partials (L2-hot, 4 KB)
    if (tid < H_) {
        float w = 0.f;
        #pragma unroll
        for (int d = 0; d < 8; ++d) w += __ldcg(&g_wpart[d * H_ + tid]);
        sh_wcol[tid] = w;
    }
    __syncthreads();

    const float4 w4 = reinterpret_cast<const float4*>(sh_wcol)[lane];
    float acc = k4.x * w4.x + k4.y * w4.y + k4.z * w4.z + k4.w * w4.w;
    #pragma unroll
    for (int o = 16; o > 0; o >>= 1) acc += __shfl_xor_sync(0xffffffffu, acc, o);
    if (lane == 0) {
        const float e = __expf(SCALE_ * acc);
        __stcg(&g_es[row], e);
        sh_e[warp] = e;
    }
    __syncthreads();
    if (warp == 0) {
        float v = sh_e[lane];
        #pragma unroll
        for (int o = 16; o > 0; o >>= 1) v += __shfl_xor_sync(0xffffffffu, v, o);
        if (lane == 0) __stcg(&g_psum[blk], v);  // blocks 0..31 batch0, 32..63 batch1
    }
}

// ---------------------------------------------------------------------------
// K2: prologue loads values (overlaps K1), then denom + scale + output.
// grid 128 x 1024; block b handles output rows [b*16, b*16+16).
// ---------------------------------------------------------------------------
__global__ __launch_bounds__(1024) void k_out(const float* __restrict__ values,
                                              float* __restrict__ out) {
    __shared__ float sh_val[16];

    const int tid  = threadIdx.x;
    const int lane = tid & 31;
    const int blk  = blockIdx.x;

    // prologue: cold values read, overlapped with K0/K1 execution
    if (tid < 16) sh_val[tid] = values[blk * 16 + tid];
    __syncthreads();

    // wait for K1 grid completion
    cudaGridDependencySynchronize();

    const int b   = blk >> 6;                    // 64 blocks per batch
    const int col = tid & 255;
    const int q   = tid >> 8;
    const float4 e4 = __ldcg(
        reinterpret_cast<const float4*>(g_es) + (b << 8) + col);

    float p = __ldcg(&g_psum[b * 32 + lane]);    // 32 partials per batch
    #pragma unroll
    for (int o = 16; o > 0; o >>= 1) p += __shfl_xor_sync(0xffffffffu, p, o);
    const float inv = 1.0f / p;
    const float4 s4 = make_float4(e4.x * inv, e4.y * inv, e4.z * inv, e4.w * inv);

    float4* o4 = reinterpret_cast<float4*>(out);
    #pragma unroll
    for (int i = 0; i < 4; ++i) {
        const int rl = i * 4 + q;
        const float v = sh_val[rl];
        o4[(size_t)(blk * 16 + rl) * 256 + col] =
            make_float4(s4.x * v, s4.y * v, s4.z * v, s4.w * v);
    }
}

extern "C" void kernel_launch(void* const* d_in, const int* in_sizes, int n_in,
                              void* d_out, int out_size) {
    // metadata order: queries, keys, values, W, b (queries & bias cancel in softmax)
    const float* keys   = (const float*)d_in[1];
    const float* values = (const float*)d_in[2];
    const float* W      = (const float*)d_in[3];
    float* out = (float*)d_out;

    // K0: plain launch
    k_wpart<<<8, 512>>>(W);

    cudaLaunchAttribute attrs[1];
    attrs[0].id = cudaLaunchAttributeProgrammaticStreamSerialization;
    attrs[0].val.programmaticStreamSerializationAllowed = 1;

    // K1: PDL on K0
    {
        cudaLaunchConfig_t cfg = {};
        cfg.gridDim = dim3(64, 1, 1);
        cfg.blockDim = dim3(1024, 1, 1);
        cfg.attrs = attrs;
        cfg.numAttrs = 1;
        cudaLaunchKernelEx(&cfg, k_exps, keys);
    }
    // K2: PDL on K1
    {
        cudaLaunchConfig_t cfg = {};
        cfg.gridDim = dim3(128, 1, 1);
        cfg.blockDim = dim3(1024, 1, 1);
        cfg.attrs = attrs;
        cfg.numAttrs = 1;
        cudaLaunchKernelEx(&cfg, k_out, values, out);
    }
}